// round 7
// baseline (speedup 1.0000x reference)
#include <cuda_runtime.h>
#include <cuda_bf16.h>
#include <cstdint>
#include <math.h>

#define DMODEL 1024
#define NHEADS 16
#define DK     64
#define SEQ    2048
#define BATCH  2
#define MTOT   (BATCH*SEQ)   // 4096

// ---------------------------------------------------------------------------
// Global bf16 scratch (hi/lo split pairs)
// ---------------------------------------------------------------------------
__device__ __nv_bfloat16 g_xh[MTOT*DMODEL], g_xl[MTOT*DMODEL];
__device__ __nv_bfloat16 g_wh[4*DMODEL*DMODEL], g_wl[4*DMODEL*DMODEL];
__device__ __nv_bfloat16 g_qh[MTOT*DMODEL], g_ql[MTOT*DMODEL];
__device__ __nv_bfloat16 g_kh[MTOT*DMODEL], g_kl[MTOT*DMODEL];
__device__ __nv_bfloat16 g_vh[MTOT*DMODEL], g_vl[MTOT*DMODEL];
__device__ __nv_bfloat16 g_ah[MTOT*DMODEL], g_al[MTOT*DMODEL];

// ---------------------------------------------------------------------------
// Helpers
// ---------------------------------------------------------------------------
static __device__ __forceinline__ uint32_t s2u(const void* p) {
    uint32_t a;
    asm("{ .reg .u64 t; cvta.to.shared.u64 t, %1; cvt.u32.u64 %0, t; }"
        : "=r"(a) : "l"(p));
    return a;
}

#define CPA(dst, src) \
    asm volatile("cp.async.cg.shared.global [%0], [%1], 16;" \
                 :: "r"(dst), "l"(__cvta_generic_to_global(src)) : "memory")
#define CPC() asm volatile("cp.async.commit_group;" ::: "memory")
#define CPW(n) asm volatile("cp.async.wait_group %0;" :: "n"(n) : "memory")

static __device__ __forceinline__ void mma_bf16(float* c, const uint32_t* a,
                                                const uint32_t* b) {
    asm volatile(
        "mma.sync.aligned.m16n8k16.row.col.f32.bf16.bf16.f32 "
        "{%0,%1,%2,%3}, {%4,%5,%6,%7}, {%8,%9}, {%0,%1,%2,%3};"
        : "+f"(c[0]), "+f"(c[1]), "+f"(c[2]), "+f"(c[3])
        : "r"(a[0]), "r"(a[1]), "r"(a[2]), "r"(a[3]), "r"(b[0]), "r"(b[1]));
}

static __device__ __forceinline__ void ldmx4(uint32_t* r, uint32_t a) {
    asm volatile(
        "ldmatrix.sync.aligned.m8n8.x4.shared.b16 {%0,%1,%2,%3}, [%4];"
        : "=r"(r[0]), "=r"(r[1]), "=r"(r[2]), "=r"(r[3]) : "r"(a));
}

static __device__ __forceinline__ void ldmx4t(uint32_t& r0, uint32_t& r1,
                                              uint32_t& r2, uint32_t& r3,
                                              uint32_t a) {
    asm volatile(
        "ldmatrix.sync.aligned.m8n8.x4.trans.shared.b16 {%0,%1,%2,%3}, [%4];"
        : "=r"(r0), "=r"(r1), "=r"(r2), "=r"(r3) : "r"(a));
}

static __device__ __forceinline__ void splitf(float v, __nv_bfloat16& h,
                                              __nv_bfloat16& l) {
    h = __float2bfloat16_rn(v);
    l = __float2bfloat16_rn(v - __bfloat162float(h));
}

static __device__ __forceinline__ uint32_t packbf(__nv_bfloat16 lo, __nv_bfloat16 hi) {
    __nv_bfloat162 t;
    t.x = lo; t.y = hi;
    return *(uint32_t*)&t;
}

// ---------------------------------------------------------------------------
// Split kernel: fp32 -> bf16 hi/lo for x and all 4 weights. 8192 blocks.
// ---------------------------------------------------------------------------
__global__ void __launch_bounds__(256)
split_kernel(const float* __restrict__ x,  const float* __restrict__ wq,
             const float* __restrict__ wk, const float* __restrict__ wv,
             const float* __restrict__ wo)
{
    int bid = blockIdx.x;
    const float4* src;
    uint2 *dh, *dl;
    int idx;
    if (bid < 4096) {
        src = (const float4*)x; dh = (uint2*)g_xh; dl = (uint2*)g_xl; idx = bid;
    } else {
        int t = bid - 4096;
        int w = t >> 10;
        idx = t & 1023;
        const float* ws = (w == 0) ? wq : (w == 1) ? wk : (w == 2) ? wv : wo;
        src = (const float4*)ws;
        dh = (uint2*)(g_wh + ((size_t)w << 20));
        dl = (uint2*)(g_wl + ((size_t)w << 20));
    }
    int i = idx * 256 + threadIdx.x;
    float4 v = src[i];
    __nv_bfloat16 h0, l0, h1, l1, h2, l2, h3, l3;
    splitf(v.x, h0, l0); splitf(v.y, h1, l1);
    splitf(v.z, h2, l2); splitf(v.w, h3, l3);
    dh[i] = make_uint2(packbf(h0, h1), packbf(h2, h3));
    dl[i] = make_uint2(packbf(l0, l1), packbf(l2, l3));
}

// ---------------------------------------------------------------------------
// bf16-split GEMM, pre-split inputs, cp.async double buffer, ldmatrix frags.
// C[M,N] = A[M,K] * W[N,K]^T, CTA 128x128, BK=32, 8 warps (4x2).
// ---------------------------------------------------------------------------
#define RS 40                            // bf16 elems per smem row (80 bytes)
#define GA_STAGE 10240                   // bytes per array per stage
#define G_STAGE  40960
#define GEMM_SMEM (2*G_STAGE)            // 81920

template<bool SPLIT_OUT>
static __device__ void gemm_core(const __nv_bfloat16* __restrict__ Ah,
                                 const __nv_bfloat16* __restrict__ Al,
                                 const __nv_bfloat16* __restrict__ Bh,
                                 const __nv_bfloat16* __restrict__ Bl,
                                 __nv_bfloat16* __restrict__ Ch,
                                 __nv_bfloat16* __restrict__ Cl,
                                 float* __restrict__ Cf)
{
    extern __shared__ char smem[];
    const uint32_t sb = s2u(smem);
    const int tid  = threadIdx.x;
    const int lane = tid & 31;
    const int warp = tid >> 5;
    const int wy = warp >> 1, wx = warp & 1;
    const int gi = lane >> 2, tg = lane & 3;
    const int row0 = blockIdx.y * 128;
    const int col0 = blockIdx.x * 128;

    // ldmatrix lane offsets (bytes, within an array)
    const uint32_t a_lrow = (uint32_t)((wy * 32 + (lane & 15)) * 80);
    const uint32_t b_lrow = (uint32_t)((wx * 64 + (lane & 7) + ((lane >> 3) & 1) * 8) * 80);
    const uint32_t l_colb = (uint32_t)((lane >> 4) * 16);   // +8 cols = +16B

    float acc[2][8][4];
#pragma unroll
    for (int mt = 0; mt < 2; mt++)
#pragma unroll
        for (int nt = 0; nt < 8; nt++)
#pragma unroll
            for (int r = 0; r < 4; r++) acc[mt][nt][r] = 0.0f;

#define GEMM_LOAD(kc, s)                                                     \
    {                                                                        \
        uint32_t d0 = sb + (uint32_t)(s) * G_STAGE;                          \
        _Pragma("unroll")                                                    \
        for (int c = 0; c < 2; c++) {                                        \
            int f = tid + c * 256;                                           \
            int row = f >> 2, seg = f & 3;                                   \
            size_t goA = (size_t)(row0 + row) * 1024 + (kc) * 32 + seg * 8;  \
            size_t goB = (size_t)(col0 + row) * 1024 + (kc) * 32 + seg * 8;  \
            uint32_t so = (uint32_t)(row * 80 + seg * 16);                   \
            CPA(d0 + so,                Ah + goA);                           \
            CPA(d0 + GA_STAGE + so,     Al + goA);                           \
            CPA(d0 + 2 * GA_STAGE + so, Bh + goB);                           \
            CPA(d0 + 3 * GA_STAGE + so, Bl + goB);                           \
        }                                                                    \
    }

    GEMM_LOAD(0, 0);
    CPC();

#pragma unroll 1
    for (int kc = 0; kc < 32; kc++) {
        const int s = kc & 1;
        __syncthreads();
        if (kc + 1 < 32) { GEMM_LOAD(kc + 1, s ^ 1); CPC(); CPW(1); }
        else             { CPW(0); }
        __syncthreads();

        const uint32_t base = sb + (uint32_t)s * G_STAGE;
        const uint32_t bAh = base,                 bAl = base + GA_STAGE;
        const uint32_t bBh = base + 2 * GA_STAGE,  bBl = base + 3 * GA_STAGE;

#pragma unroll
        for (int ks = 0; ks < 2; ks++) {
            const uint32_t cb2 = (uint32_t)(ks * 32) + l_colb;  // k offset bytes

            uint32_t afh[2][4], afl[2][4];
            ldmx4(afh[0], bAh + a_lrow + cb2);
            ldmx4(afh[1], bAh + a_lrow + 16 * 80 + cb2);
            ldmx4(afl[0], bAl + a_lrow + cb2);
            ldmx4(afl[1], bAl + a_lrow + 16 * 80 + cb2);

            uint32_t bh4[4][4], bl4[4][4];
#pragma unroll
            for (int g = 0; g < 4; g++) {
                ldmx4(bh4[g], bBh + b_lrow + (uint32_t)(g * 16 * 80) + cb2);
                ldmx4(bl4[g], bBl + b_lrow + (uint32_t)(g * 16 * 80) + cb2);
            }

#pragma unroll
            for (int g = 0; g < 4; g++)
#pragma unroll
                for (int hf = 0; hf < 2; hf++) {
                    const int nt = 2 * g + hf;
                    uint32_t bfh[2] = { bh4[g][hf], bh4[g][hf + 2] };
                    uint32_t bfl[2] = { bl4[g][hf], bl4[g][hf + 2] };
#pragma unroll
                    for (int mt = 0; mt < 2; mt++) {
                        mma_bf16(acc[mt][nt], afh[mt], bfh);
                        mma_bf16(acc[mt][nt], afl[mt], bfh);
                        mma_bf16(acc[mt][nt], afh[mt], bfl);
                    }
                }
        }
    }

    // epilogue
#pragma unroll
    for (int mt = 0; mt < 2; mt++) {
        int r0g = row0 + wy * 32 + mt * 16 + gi;
#pragma unroll
        for (int nt = 0; nt < 8; nt++) {
            int cg = col0 + wx * 64 + nt * 8 + 2 * tg;
            if (SPLIT_OUT) {
                __nv_bfloat16 h0, l0, h1, l1;
                splitf(acc[mt][nt][0], h0, l0);
                splitf(acc[mt][nt][1], h1, l1);
                *(uint32_t*)&Ch[(size_t)r0g * 1024 + cg] = packbf(h0, h1);
                *(uint32_t*)&Cl[(size_t)r0g * 1024 + cg] = packbf(l0, l1);
                splitf(acc[mt][nt][2], h0, l0);
                splitf(acc[mt][nt][3], h1, l1);
                *(uint32_t*)&Ch[(size_t)(r0g + 8) * 1024 + cg] = packbf(h0, h1);
                *(uint32_t*)&Cl[(size_t)(r0g + 8) * 1024 + cg] = packbf(l0, l1);
            } else {
                *(float2*)&Cf[(size_t)r0g * 1024 + cg] =
                    make_float2(acc[mt][nt][0], acc[mt][nt][1]);
                *(float2*)&Cf[(size_t)(r0g + 8) * 1024 + cg] =
                    make_float2(acc[mt][nt][2], acc[mt][nt][3]);
            }
        }
    }
#undef GEMM_LOAD
}

__global__ void __launch_bounds__(256, 2)
proj_kernel()
{
    int z = blockIdx.z;
    const __nv_bfloat16* Bh = g_wh + ((size_t)z << 20);
    const __nv_bfloat16* Bl = g_wl + ((size_t)z << 20);
    __nv_bfloat16* Ch = (z == 0) ? g_qh : (z == 1) ? g_kh : g_vh;
    __nv_bfloat16* Cl = (z == 0) ? g_ql : (z == 1) ? g_kl : g_vl;
    gemm_core<true>(g_xh, g_xl, Bh, Bl, Ch, Cl, nullptr);
}

__global__ void __launch_bounds__(256, 2)
oproj_kernel(float* __restrict__ out)
{
    gemm_core<false>(g_ah, g_al, g_wh + ((size_t)3 << 20), g_wl + ((size_t)3 << 20),
                     nullptr, nullptr, out);
}

// ---------------------------------------------------------------------------
// Tensor-core flash attention (causal). CTA = 128 q rows, 8 warps x 16 rows,
// key tiles of 64, bf16 3-pass mma, register-resident P fragments,
// ldmatrix fragment loads for Q/K/V.
// ---------------------------------------------------------------------------
#define AQH 0
#define AQL 18432
#define AKV0 36864
#define AKV_STAGE 36864
#define ATTN_SMEM (AKV0 + 2*AKV_STAGE)    // 110592

__global__ void __launch_bounds__(256, 2)
attn_kernel()
{
    extern __shared__ char smem[];
    const uint32_t sb = s2u(smem);
    const int tid  = threadIdx.x;
    const int lane = tid & 31;
    const int warp = tid >> 5;
    const int gi = lane >> 2, tg = lane & 3;

    const int qt = (int)gridDim.x - 1 - (int)blockIdx.x;   // big tiles first
    const int bh = blockIdx.y;
    const int b  = bh >> 4;
    const int h  = bh & 15;
    const size_t hoff = (size_t)b * SEQ * DMODEL + h * DK;

    const __nv_bfloat16* Qh = g_qh + hoff;
    const __nv_bfloat16* Ql = g_ql + hoff;
    const __nv_bfloat16* Kh = g_kh + hoff;
    const __nv_bfloat16* Kl = g_kl + hoff;
    const __nv_bfloat16* Vh = g_vh + hoff;
    const __nv_bfloat16* Vl = g_vl + hoff;

    const int row_base = qt * 128;
    const int ntiles = 2 * qt + 2;

    // prologue: Q tile (128x64 hi+lo)
#pragma unroll
    for (int c = 0; c < 4; c++) {
        int f = tid + c * 256;
        int row = f >> 3, seg = f & 7;
        size_t go = (size_t)(row_base + row) * 1024 + seg * 8;
        uint32_t so = (uint32_t)(row * 144 + seg * 16);
        CPA(sb + AQH + so, Qh + go);
        CPA(sb + AQL + so, Ql + go);
    }

#define LOAD_KV(jt, s)                                                     \
    {                                                                      \
        uint32_t d0 = sb + AKV0 + (uint32_t)(s) * AKV_STAGE;               \
        _Pragma("unroll")                                                  \
        for (int c = 0; c < 2; c++) {                                      \
            int f = tid + c * 256;                                         \
            int row = f >> 3, seg = f & 7;                                 \
            size_t go = (size_t)((jt) * 64 + row) * 1024 + seg * 8;        \
            uint32_t so = (uint32_t)(row * 144 + seg * 16);                \
            CPA(d0 + so,         Kh + go);                                 \
            CPA(d0 + 9216 + so,  Kl + go);                                 \
            CPA(d0 + 18432 + so, Vh + go);                                 \
            CPA(d0 + 27648 + so, Vl + go);                                 \
        }                                                                  \
    }

    LOAD_KV(0, 0);
    CPC();

    float o[8][4];
#pragma unroll
    for (int nt = 0; nt < 8; nt++)
#pragma unroll
        for (int r = 0; r < 4; r++) o[nt][r] = 0.0f;
    float m0 = -1e30f, m1 = -1e30f, l0v = 0.0f, l1v = 0.0f;

    const int r0 = warp * 16 + gi;     // local q row
    const int r1 = r0 + 8;
    const int grow0 = row_base + r0;
    const int grow1 = row_base + r1;

    // ldmatrix lane offsets for Q (A-op) and K (B-op), 144-byte rows
    const uint32_t q_lrow = (uint32_t)((warp * 16 + (lane & 15)) * 144);
    const uint32_t k_lrow = (uint32_t)(((lane & 7) + ((lane >> 3) & 1) * 8) * 144);
    const uint32_t l_colb = (uint32_t)((lane >> 4) * 16);

    // V ldmatrix (trans) lane addressing
    const int vrow_off = ((lane >> 3) & 1) * 8 + (lane & 7);
    const uint32_t vcolb = (uint32_t)((lane >> 4) * 16);

#pragma unroll 1
    for (int jt = 0; jt < ntiles; jt++) {
        const int s = jt & 1;
        __syncthreads();
        if (jt + 1 < ntiles) { LOAD_KV(jt + 1, s ^ 1); CPC(); CPW(1); }
        else                 { CPW(0); }
        __syncthreads();

        const uint32_t bKh = sb + AKV0 + (uint32_t)s * AKV_STAGE;
        const uint32_t bKl = bKh + 9216;

        // ---- S = Q K^T (16 rows x 64 keys per warp) ----
        float sv[8][4];
#pragma unroll
        for (int nt = 0; nt < 8; nt++)
#pragma unroll
            for (int r = 0; r < 4; r++) sv[nt][r] = 0.0f;

#pragma unroll
        for (int ks = 0; ks < 4; ks++) {
            const uint32_t cb2 = (uint32_t)(ks * 32) + l_colb;
            uint32_t ah_[4], al_[4];
            ldmx4(ah_, sb + AQH + q_lrow + cb2);
            ldmx4(al_, sb + AQL + q_lrow + cb2);
#pragma unroll
            for (int g = 0; g < 4; g++) {
                uint32_t kh4[4], kl4[4];
                ldmx4(kh4, bKh + k_lrow + (uint32_t)(g * 16 * 144) + cb2);
                ldmx4(kl4, bKl + k_lrow + (uint32_t)(g * 16 * 144) + cb2);
#pragma unroll
                for (int hf = 0; hf < 2; hf++) {
                    uint32_t bh_[2] = { kh4[hf], kh4[hf + 2] };
                    uint32_t bl_[2] = { kl4[hf], kl4[hf + 2] };
                    mma_bf16(sv[2 * g + hf], ah_, bh_);
                    mma_bf16(sv[2 * g + hf], al_, bh_);
                    mma_bf16(sv[2 * g + hf], ah_, bl_);
                }
            }
        }

        // ---- scale + causal mask ----
        const bool maskt = (jt >= 2 * qt);
#pragma unroll
        for (int nt = 0; nt < 8; nt++) {
            sv[nt][0] *= 0.125f; sv[nt][1] *= 0.125f;
            sv[nt][2] *= 0.125f; sv[nt][3] *= 0.125f;
            if (maskt) {
                int c0 = jt * 64 + nt * 8 + 2 * tg;
                if (c0     > grow0) sv[nt][0] = -1e30f;
                if (c0 + 1 > grow0) sv[nt][1] = -1e30f;
                if (c0     > grow1) sv[nt][2] = -1e30f;
                if (c0 + 1 > grow1) sv[nt][3] = -1e30f;
            }
        }

        // ---- online softmax (2 rows/thread, quad reduction) ----
        float mx0 = -1e30f, mx1 = -1e30f;
#pragma unroll
        for (int nt = 0; nt < 8; nt++) {
            mx0 = fmaxf(mx0, fmaxf(sv[nt][0], sv[nt][1]));
            mx1 = fmaxf(mx1, fmaxf(sv[nt][2], sv[nt][3]));
        }
        mx0 = fmaxf(mx0, __shfl_xor_sync(0xffffffffu, mx0, 1));
        mx0 = fmaxf(mx0, __shfl_xor_sync(0xffffffffu, mx0, 2));
        mx1 = fmaxf(mx1, __shfl_xor_sync(0xffffffffu, mx1, 1));
        mx1 = fmaxf(mx1, __shfl_xor_sync(0xffffffffu, mx1, 2));
        float nm0 = fmaxf(m0, mx0), nm1 = fmaxf(m1, mx1);
        float e0 = __expf(m0 - nm0), e1 = __expf(m1 - nm1);
        float rs0 = 0.0f, rs1 = 0.0f;
#pragma unroll
        for (int nt = 0; nt < 8; nt++) {
            sv[nt][0] = __expf(sv[nt][0] - nm0); rs0 += sv[nt][0];
            sv[nt][1] = __expf(sv[nt][1] - nm0); rs0 += sv[nt][1];
            sv[nt][2] = __expf(sv[nt][2] - nm1); rs1 += sv[nt][2];
            sv[nt][3] = __expf(sv[nt][3] - nm1); rs1 += sv[nt][3];
        }
        rs0 += __shfl_xor_sync(0xffffffffu, rs0, 1);
        rs0 += __shfl_xor_sync(0xffffffffu, rs0, 2);
        rs1 += __shfl_xor_sync(0xffffffffu, rs1, 1);
        rs1 += __shfl_xor_sync(0xffffffffu, rs1, 2);
        l0v = l0v * e0 + rs0;
        l1v = l1v * e1 + rs1;
        m0 = nm0; m1 = nm1;
#pragma unroll
        for (int nt = 0; nt < 8; nt++) {
            o[nt][0] *= e0; o[nt][1] *= e0;
            o[nt][2] *= e1; o[nt][3] *= e1;
        }

        // ---- O += P @ V (P fragments straight from S accumulators) ----
        const uint32_t vbase_h = sb + AKV0 + (uint32_t)s * AKV_STAGE + 18432;
        const uint32_t vbase_l = vbase_h + 9216;
#pragma unroll
        for (int ks = 0; ks < 4; ks++) {
            uint32_t ph[4], pl[4];
            {
                __nv_bfloat16 ha, la, hb, lb;
                splitf(sv[2*ks][0], ha, la); splitf(sv[2*ks][1], hb, lb);
                ph[0] = packbf(ha, hb); pl[0] = packbf(la, lb);
                splitf(sv[2*ks][2], ha, la); splitf(sv[2*ks][3], hb, lb);
                ph[1] = packbf(ha, hb); pl[1] = packbf(la, lb);
                splitf(sv[2*ks+1][0], ha, la); splitf(sv[2*ks+1][1], hb, lb);
                ph[2] = packbf(ha, hb); pl[2] = packbf(la, lb);
                splitf(sv[2*ks+1][2], ha, la); splitf(sv[2*ks+1][3], hb, lb);
                ph[3] = packbf(ha, hb); pl[3] = packbf(la, lb);
            }
            const uint32_t vrow = (uint32_t)(16 * ks + vrow_off);
#pragma unroll
            for (int p2 = 0; p2 < 4; p2++) {
                uint32_t off = vrow * 144 + (uint32_t)p2 * 32 + vcolb;
                uint32_t h0, h1, h2, h3, q0, q1, q2, q3;
                ldmx4t(h0, h1, h2, h3, vbase_h + off);
                ldmx4t(q0, q1, q2, q3, vbase_l + off);
                uint32_t bbh[2], bbl[2];
                bbh[0] = h0; bbh[1] = h1; bbl[0] = q0; bbl[1] = q1;
                mma_bf16(o[2*p2], ph, bbh);
                mma_bf16(o[2*p2], pl, bbh);
                mma_bf16(o[2*p2], ph, bbl);
                bbh[0] = h2; bbh[1] = h3; bbl[0] = q2; bbl[1] = q3;
                mma_bf16(o[2*p2+1], ph, bbh);
                mma_bf16(o[2*p2+1], pl, bbh);
                mma_bf16(o[2*p2+1], ph, bbl);
            }
        }
    }
#undef LOAD_KV

    // ---- epilogue: normalize, split, store bf16 hi/lo ----
    const float inv0 = 1.0f / l0v, inv1 = 1.0f / l1v;
    __nv_bfloat16* Oh = g_ah + hoff;
    __nv_bfloat16* Ol = g_al + hoff;
#pragma unroll
    for (int nt = 0; nt < 8; nt++) {
        int cg = nt * 8 + 2 * tg;
        __nv_bfloat16 ha, la, hb, lb;
        splitf(o[nt][0] * inv0, ha, la);
        splitf(o[nt][1] * inv0, hb, lb);
        *(uint32_t*)&Oh[(size_t)grow0 * 1024 + cg] = packbf(ha, hb);
        *(uint32_t*)&Ol[(size_t)grow0 * 1024 + cg] = packbf(la, lb);
        splitf(o[nt][2] * inv1, ha, la);
        splitf(o[nt][3] * inv1, hb, lb);
        *(uint32_t*)&Oh[(size_t)grow1 * 1024 + cg] = packbf(ha, hb);
        *(uint32_t*)&Ol[(size_t)grow1 * 1024 + cg] = packbf(la, lb);
    }
}

// ---------------------------------------------------------------------------
extern "C" void kernel_launch(void* const* d_in, const int* in_sizes, int n_in,
                              void* d_out, int out_size)
{
    (void)in_sizes; (void)n_in; (void)out_size;
    const float* x  = (const float*)d_in[0];
    const float* wq = (const float*)d_in[1];
    const float* wk = (const float*)d_in[2];
    const float* wv = (const float*)d_in[3];
    const float* wo = (const float*)d_in[4];
    float* out = (float*)d_out;

    cudaFuncSetAttribute(proj_kernel,
                         cudaFuncAttributeMaxDynamicSharedMemorySize, GEMM_SMEM);
    cudaFuncSetAttribute(oproj_kernel,
                         cudaFuncAttributeMaxDynamicSharedMemorySize, GEMM_SMEM);
    cudaFuncSetAttribute(attn_kernel,
                         cudaFuncAttributeMaxDynamicSharedMemorySize, ATTN_SMEM);

    split_kernel<<<8192, 256>>>(x, wq, wk, wv, wo);
    proj_kernel<<<dim3(8, 32, 3), 256, GEMM_SMEM>>>();
    attn_kernel<<<dim3(16, 32), 256, ATTN_SMEM>>>();
    oproj_kernel<<<dim3(8, 32), 256, GEMM_SMEM>>>(out);
}

// round 8
// speedup vs baseline: 1.0531x; 1.0531x over previous
#include <cuda_runtime.h>
#include <cuda_bf16.h>
#include <cstdint>
#include <math.h>

#define DMODEL 1024
#define NHEADS 16
#define DK     64
#define SEQ    2048
#define BATCH  2
#define MTOT   (BATCH*SEQ)   // 4096

// ---------------------------------------------------------------------------
// Global bf16 scratch (hi/lo split pairs)
// ---------------------------------------------------------------------------
__device__ __nv_bfloat16 g_xh[MTOT*DMODEL], g_xl[MTOT*DMODEL];
__device__ __nv_bfloat16 g_wh[4*DMODEL*DMODEL], g_wl[4*DMODEL*DMODEL];
__device__ __nv_bfloat16 g_qh[MTOT*DMODEL], g_ql[MTOT*DMODEL];
__device__ __nv_bfloat16 g_kh[MTOT*DMODEL], g_kl[MTOT*DMODEL];
__device__ __nv_bfloat16 g_vh[MTOT*DMODEL], g_vl[MTOT*DMODEL];
__device__ __nv_bfloat16 g_ah[MTOT*DMODEL], g_al[MTOT*DMODEL];

// ---------------------------------------------------------------------------
// Helpers
// ---------------------------------------------------------------------------
static __device__ __forceinline__ uint32_t s2u(const void* p) {
    uint32_t a;
    asm("{ .reg .u64 t; cvta.to.shared.u64 t, %1; cvt.u32.u64 %0, t; }"
        : "=r"(a) : "l"(p));
    return a;
}

#define CPA(dst, src) \
    asm volatile("cp.async.cg.shared.global [%0], [%1], 16;" \
                 :: "r"(dst), "l"(__cvta_generic_to_global(src)) : "memory")
#define CPC() asm volatile("cp.async.commit_group;" ::: "memory")
#define CPW(n) asm volatile("cp.async.wait_group %0;" :: "n"(n) : "memory")

static __device__ __forceinline__ void mma_bf16(float* c, const uint32_t* a,
                                                const uint32_t* b) {
    asm volatile(
        "mma.sync.aligned.m16n8k16.row.col.f32.bf16.bf16.f32 "
        "{%0,%1,%2,%3}, {%4,%5,%6,%7}, {%8,%9}, {%0,%1,%2,%3};"
        : "+f"(c[0]), "+f"(c[1]), "+f"(c[2]), "+f"(c[3])
        : "r"(a[0]), "r"(a[1]), "r"(a[2]), "r"(a[3]), "r"(b[0]), "r"(b[1]));
}

static __device__ __forceinline__ void ldmx4t(uint32_t& r0, uint32_t& r1,
                                              uint32_t& r2, uint32_t& r3,
                                              uint32_t a) {
    asm volatile(
        "ldmatrix.sync.aligned.m8n8.x4.trans.shared.b16 {%0,%1,%2,%3}, [%4];"
        : "=r"(r0), "=r"(r1), "=r"(r2), "=r"(r3) : "r"(a));
}

static __device__ __forceinline__ void splitf(float v, __nv_bfloat16& h,
                                              __nv_bfloat16& l) {
    h = __float2bfloat16_rn(v);
    l = __float2bfloat16_rn(v - __bfloat162float(h));
}

static __device__ __forceinline__ uint32_t packbf(__nv_bfloat16 lo, __nv_bfloat16 hi) {
    __nv_bfloat162 t;
    t.x = lo; t.y = hi;
    return *(uint32_t*)&t;
}

// ---------------------------------------------------------------------------
// Split kernel: fp32 -> bf16 hi/lo for x and all 4 weights. 8192 blocks.
// ---------------------------------------------------------------------------
__global__ void __launch_bounds__(256)
split_kernel(const float* __restrict__ x,  const float* __restrict__ wq,
             const float* __restrict__ wk, const float* __restrict__ wv,
             const float* __restrict__ wo)
{
    int bid = blockIdx.x;
    const float4* src;
    uint2 *dh, *dl;
    int idx;
    if (bid < 4096) {
        src = (const float4*)x; dh = (uint2*)g_xh; dl = (uint2*)g_xl; idx = bid;
    } else {
        int t = bid - 4096;
        int w = t >> 10;
        idx = t & 1023;
        const float* ws = (w == 0) ? wq : (w == 1) ? wk : (w == 2) ? wv : wo;
        src = (const float4*)ws;
        dh = (uint2*)(g_wh + ((size_t)w << 20));
        dl = (uint2*)(g_wl + ((size_t)w << 20));
    }
    int i = idx * 256 + threadIdx.x;
    float4 v = src[i];
    __nv_bfloat16 h0, l0, h1, l1, h2, l2, h3, l3;
    splitf(v.x, h0, l0); splitf(v.y, h1, l1);
    splitf(v.z, h2, l2); splitf(v.w, h3, l3);
    dh[i] = make_uint2(packbf(h0, h1), packbf(h2, h3));
    dl[i] = make_uint2(packbf(l0, l1), packbf(l2, l3));
}

// ---------------------------------------------------------------------------
// bf16-split GEMM, pre-split inputs, cp.async double buffer, ONE barrier/chunk,
// pass-major mma ordering. C[M,N] = A[M,K]*W[N,K]^T, CTA 128x128, BK=32.
// ---------------------------------------------------------------------------
#define RS 40
#define GA_STAGE 10240                   // bytes per array per stage
#define G_STAGE  40960
#define GEMM_SMEM (2*G_STAGE)            // 81920

template<bool SPLIT_OUT>
static __device__ void gemm_core(const __nv_bfloat16* __restrict__ Ah,
                                 const __nv_bfloat16* __restrict__ Al,
                                 const __nv_bfloat16* __restrict__ Bh,
                                 const __nv_bfloat16* __restrict__ Bl,
                                 __nv_bfloat16* __restrict__ Ch,
                                 __nv_bfloat16* __restrict__ Cl,
                                 float* __restrict__ Cf)
{
    extern __shared__ char smem[];
    const uint32_t sb = s2u(smem);
    const int tid  = threadIdx.x;
    const int lane = tid & 31;
    const int warp = tid >> 5;
    const int wy = warp >> 1, wx = warp & 1;
    const int gi = lane >> 2, tg = lane & 3;
    const int row0 = blockIdx.y * 128;
    const int col0 = blockIdx.x * 128;

    float acc[2][8][4];
#pragma unroll
    for (int mt = 0; mt < 2; mt++)
#pragma unroll
        for (int nt = 0; nt < 8; nt++)
#pragma unroll
            for (int r = 0; r < 4; r++) acc[mt][nt][r] = 0.0f;

#define GEMM_LOAD(kc, s)                                                     \
    {                                                                        \
        uint32_t d0 = sb + (uint32_t)(s) * G_STAGE;                          \
        _Pragma("unroll")                                                    \
        for (int c = 0; c < 2; c++) {                                        \
            int f = tid + c * 256;                                           \
            int row = f >> 2, seg = f & 3;                                   \
            size_t goA = (size_t)(row0 + row) * 1024 + (kc) * 32 + seg * 8;  \
            size_t goB = (size_t)(col0 + row) * 1024 + (kc) * 32 + seg * 8;  \
            uint32_t so = (uint32_t)(row * 80 + seg * 16);                   \
            CPA(d0 + so,                Ah + goA);                           \
            CPA(d0 + GA_STAGE + so,     Al + goA);                           \
            CPA(d0 + 2 * GA_STAGE + so, Bh + goB);                           \
            CPA(d0 + 3 * GA_STAGE + so, Bl + goB);                           \
        }                                                                    \
    }

    GEMM_LOAD(0, 0);
    CPC();

#pragma unroll 1
    for (int kc = 0; kc < 32; kc++) {
        const int s = kc & 1;
        // wait for MY loads of stage s, then barrier: (i) everyone's stage-s
        // data visible, (ii) everyone finished computing on stage s^1.
        CPW(0);
        __syncthreads();
        if (kc + 1 < 32) { GEMM_LOAD(kc + 1, s ^ 1); CPC(); }

        const uint16_t* sAh = (const uint16_t*)(smem + s * G_STAGE);
        const uint16_t* sAl = sAh + 5120;
        const uint16_t* sBh = sAh + 10240;
        const uint16_t* sBl = sAh + 15360;

#pragma unroll
        for (int ks = 0; ks < 2; ks++) {
            const int cb = ks * 16 + 2 * tg;
            uint32_t afh[2][4], afl[2][4];
#pragma unroll
            for (int mt = 0; mt < 2; mt++) {
                int r = wy * 32 + mt * 16 + gi;
                afh[mt][0] = *(const uint32_t*)&sAh[r * RS + cb];
                afh[mt][1] = *(const uint32_t*)&sAh[(r + 8) * RS + cb];
                afh[mt][2] = *(const uint32_t*)&sAh[r * RS + cb + 8];
                afh[mt][3] = *(const uint32_t*)&sAh[(r + 8) * RS + cb + 8];
                afl[mt][0] = *(const uint32_t*)&sAl[r * RS + cb];
                afl[mt][1] = *(const uint32_t*)&sAl[(r + 8) * RS + cb];
                afl[mt][2] = *(const uint32_t*)&sAl[r * RS + cb + 8];
                afl[mt][3] = *(const uint32_t*)&sAl[(r + 8) * RS + cb + 8];
            }
            uint32_t bfh[8][2], bfl[8][2];
#pragma unroll
            for (int nt = 0; nt < 8; nt++) {
                int c = wx * 64 + nt * 8 + gi;
                bfh[nt][0] = *(const uint32_t*)&sBh[c * RS + cb];
                bfh[nt][1] = *(const uint32_t*)&sBh[c * RS + cb + 8];
                bfl[nt][0] = *(const uint32_t*)&sBl[c * RS + cb];
                bfl[nt][1] = *(const uint32_t*)&sBl[c * RS + cb + 8];
            }
            // pass-major: 16 independent accumulators between touches
#pragma unroll
            for (int nt = 0; nt < 8; nt++)
#pragma unroll
                for (int mt = 0; mt < 2; mt++)
                    mma_bf16(acc[mt][nt], afh[mt], bfh[nt]);
#pragma unroll
            for (int nt = 0; nt < 8; nt++)
#pragma unroll
                for (int mt = 0; mt < 2; mt++)
                    mma_bf16(acc[mt][nt], afl[mt], bfh[nt]);
#pragma unroll
            for (int nt = 0; nt < 8; nt++)
#pragma unroll
                for (int mt = 0; mt < 2; mt++)
                    mma_bf16(acc[mt][nt], afh[mt], bfl[nt]);
        }
    }

    // epilogue
#pragma unroll
    for (int mt = 0; mt < 2; mt++) {
        int r0g = row0 + wy * 32 + mt * 16 + gi;
#pragma unroll
        for (int nt = 0; nt < 8; nt++) {
            int cg = col0 + wx * 64 + nt * 8 + 2 * tg;
            if (SPLIT_OUT) {
                __nv_bfloat16 h0, l0, h1, l1;
                splitf(acc[mt][nt][0], h0, l0);
                splitf(acc[mt][nt][1], h1, l1);
                *(uint32_t*)&Ch[(size_t)r0g * 1024 + cg] = packbf(h0, h1);
                *(uint32_t*)&Cl[(size_t)r0g * 1024 + cg] = packbf(l0, l1);
                splitf(acc[mt][nt][2], h0, l0);
                splitf(acc[mt][nt][3], h1, l1);
                *(uint32_t*)&Ch[(size_t)(r0g + 8) * 1024 + cg] = packbf(h0, h1);
                *(uint32_t*)&Cl[(size_t)(r0g + 8) * 1024 + cg] = packbf(l0, l1);
            } else {
                *(float2*)&Cf[(size_t)r0g * 1024 + cg] =
                    make_float2(acc[mt][nt][0], acc[mt][nt][1]);
                *(float2*)&Cf[(size_t)(r0g + 8) * 1024 + cg] =
                    make_float2(acc[mt][nt][2], acc[mt][nt][3]);
            }
        }
    }
#undef GEMM_LOAD
}

__global__ void __launch_bounds__(256, 2)
proj_kernel()
{
    int z = blockIdx.z;
    const __nv_bfloat16* Bh = g_wh + ((size_t)z << 20);
    const __nv_bfloat16* Bl = g_wl + ((size_t)z << 20);
    __nv_bfloat16* Ch = (z == 0) ? g_qh : (z == 1) ? g_kh : g_vh;
    __nv_bfloat16* Cl = (z == 0) ? g_ql : (z == 1) ? g_kl : g_vl;
    gemm_core<true>(g_xh, g_xl, Bh, Bl, Ch, Cl, nullptr);
}

__global__ void __launch_bounds__(256, 2)
oproj_kernel(float* __restrict__ out)
{
    gemm_core<false>(g_ah, g_al, g_wh + ((size_t)3 << 20), g_wl + ((size_t)3 << 20),
                     nullptr, nullptr, out);
}

// ---------------------------------------------------------------------------
// Tensor-core flash attention (causal). CTA = 128 q rows, 8 warps x 16 rows,
// key tiles of 64, bf16 3-pass mma, register-resident P fragments,
// ONE barrier per KV tile, distance-2 mma chains.
// ---------------------------------------------------------------------------
#define AQH 0
#define AQL 18432
#define AKV0 36864
#define AKV_STAGE 36864
#define ATTN_SMEM (AKV0 + 2*AKV_STAGE)    // 110592

__global__ void __launch_bounds__(256, 2)
attn_kernel()
{
    extern __shared__ char smem[];
    const uint32_t sb = s2u(smem);
    const int tid  = threadIdx.x;
    const int lane = tid & 31;
    const int warp = tid >> 5;
    const int gi = lane >> 2, tg = lane & 3;

    const int qt = (int)gridDim.x - 1 - (int)blockIdx.x;   // big tiles first
    const int bh = blockIdx.y;
    const int b  = bh >> 4;
    const int h  = bh & 15;
    const size_t hoff = (size_t)b * SEQ * DMODEL + h * DK;

    const __nv_bfloat16* Qh = g_qh + hoff;
    const __nv_bfloat16* Ql = g_ql + hoff;
    const __nv_bfloat16* Kh = g_kh + hoff;
    const __nv_bfloat16* Kl = g_kl + hoff;
    const __nv_bfloat16* Vh = g_vh + hoff;
    const __nv_bfloat16* Vl = g_vl + hoff;

    const int row_base = qt * 128;
    const int ntiles = 2 * qt + 2;

    // prologue: Q tile (128x64 hi+lo)
#pragma unroll
    for (int c = 0; c < 4; c++) {
        int f = tid + c * 256;
        int row = f >> 3, seg = f & 7;
        size_t go = (size_t)(row_base + row) * 1024 + seg * 8;
        uint32_t so = (uint32_t)(row * 144 + seg * 16);
        CPA(sb + AQH + so, Qh + go);
        CPA(sb + AQL + so, Ql + go);
    }

#define LOAD_KV(jt, s)                                                     \
    {                                                                      \
        uint32_t d0 = sb + AKV0 + (uint32_t)(s) * AKV_STAGE;               \
        _Pragma("unroll")                                                  \
        for (int c = 0; c < 2; c++) {                                      \
            int f = tid + c * 256;                                         \
            int row = f >> 3, seg = f & 7;                                 \
            size_t go = (size_t)((jt) * 64 + row) * 1024 + seg * 8;        \
            uint32_t so = (uint32_t)(row * 144 + seg * 16);                \
            CPA(d0 + so,         Kh + go);                                 \
            CPA(d0 + 9216 + so,  Kl + go);                                 \
            CPA(d0 + 18432 + so, Vh + go);                                 \
            CPA(d0 + 27648 + so, Vl + go);                                 \
        }                                                                  \
    }

    LOAD_KV(0, 0);
    CPC();

    float o[8][4];
#pragma unroll
    for (int nt = 0; nt < 8; nt++)
#pragma unroll
        for (int r = 0; r < 4; r++) o[nt][r] = 0.0f;
    float m0 = -1e30f, m1 = -1e30f, l0v = 0.0f, l1v = 0.0f;

    const int r0 = warp * 16 + gi;     // local q row
    const int r1 = r0 + 8;
    const int grow0 = row_base + r0;
    const int grow1 = row_base + r1;

    // V ldmatrix (trans) lane addressing
    const int vrow_off = ((lane >> 3) & 1) * 8 + (lane & 7);
    const uint32_t vcolb = (uint32_t)((lane >> 4) * 16);

    const uint16_t* sQh = (const uint16_t*)(smem + AQH);
    const uint16_t* sQl = (const uint16_t*)(smem + AQL);

#pragma unroll 1
    for (int jt = 0; jt < ntiles; jt++) {
        const int s = jt & 1;
        // one barrier: my loads done -> barrier -> everyone's data visible and
        // everyone finished reading stage s^1 -> safe to prefetch into s^1.
        CPW(0);
        __syncthreads();
        if (jt + 1 < ntiles) { LOAD_KV(jt + 1, s ^ 1); CPC(); }

        const uint16_t* sKh = (const uint16_t*)(smem + AKV0 + s * AKV_STAGE);
        const uint16_t* sKl = sKh + 4608;

        // ---- S = Q K^T (16 rows x 64 keys per warp) ----
        float sv[8][4];
#pragma unroll
        for (int nt = 0; nt < 8; nt++)
#pragma unroll
            for (int r = 0; r < 4; r++) sv[nt][r] = 0.0f;

#pragma unroll
        for (int ks = 0; ks < 4; ks++) {
            const int cb = ks * 16 + 2 * tg;
            uint32_t ah_[4], al_[4];
            ah_[0] = *(const uint32_t*)&sQh[r0 * 72 + cb];
            ah_[1] = *(const uint32_t*)&sQh[r1 * 72 + cb];
            ah_[2] = *(const uint32_t*)&sQh[r0 * 72 + cb + 8];
            ah_[3] = *(const uint32_t*)&sQh[r1 * 72 + cb + 8];
            al_[0] = *(const uint32_t*)&sQl[r0 * 72 + cb];
            al_[1] = *(const uint32_t*)&sQl[r1 * 72 + cb];
            al_[2] = *(const uint32_t*)&sQl[r0 * 72 + cb + 8];
            al_[3] = *(const uint32_t*)&sQl[r1 * 72 + cb + 8];
#pragma unroll
            for (int g = 0; g < 4; g++) {
                int kr0 = (2 * g) * 8 + gi;
                int kr1 = (2 * g + 1) * 8 + gi;
                uint32_t bh0[2], bh1[2], bl0[2], bl1[2];
                bh0[0] = *(const uint32_t*)&sKh[kr0 * 72 + cb];
                bh0[1] = *(const uint32_t*)&sKh[kr0 * 72 + cb + 8];
                bh1[0] = *(const uint32_t*)&sKh[kr1 * 72 + cb];
                bh1[1] = *(const uint32_t*)&sKh[kr1 * 72 + cb + 8];
                bl0[0] = *(const uint32_t*)&sKl[kr0 * 72 + cb];
                bl0[1] = *(const uint32_t*)&sKl[kr0 * 72 + cb + 8];
                bl1[0] = *(const uint32_t*)&sKl[kr1 * 72 + cb];
                bl1[1] = *(const uint32_t*)&sKl[kr1 * 72 + cb + 8];
                // distance-2 chains
                mma_bf16(sv[2 * g],     ah_, bh0);
                mma_bf16(sv[2 * g + 1], ah_, bh1);
                mma_bf16(sv[2 * g],     al_, bh0);
                mma_bf16(sv[2 * g + 1], al_, bh1);
                mma_bf16(sv[2 * g],     ah_, bl0);
                mma_bf16(sv[2 * g + 1], ah_, bl1);
            }
        }

        // ---- scale + causal mask ----
        const bool maskt = (jt >= 2 * qt);
#pragma unroll
        for (int nt = 0; nt < 8; nt++) {
            sv[nt][0] *= 0.125f; sv[nt][1] *= 0.125f;
            sv[nt][2] *= 0.125f; sv[nt][3] *= 0.125f;
            if (maskt) {
                int c0 = jt * 64 + nt * 8 + 2 * tg;
                if (c0     > grow0) sv[nt][0] = -1e30f;
                if (c0 + 1 > grow0) sv[nt][1] = -1e30f;
                if (c0     > grow1) sv[nt][2] = -1e30f;
                if (c0 + 1 > grow1) sv[nt][3] = -1e30f;
            }
        }

        // ---- online softmax (2 rows/thread, quad reduction) ----
        float mx0 = -1e30f, mx1 = -1e30f;
#pragma unroll
        for (int nt = 0; nt < 8; nt++) {
            mx0 = fmaxf(mx0, fmaxf(sv[nt][0], sv[nt][1]));
            mx1 = fmaxf(mx1, fmaxf(sv[nt][2], sv[nt][3]));
        }
        mx0 = fmaxf(mx0, __shfl_xor_sync(0xffffffffu, mx0, 1));
        mx0 = fmaxf(mx0, __shfl_xor_sync(0xffffffffu, mx0, 2));
        mx1 = fmaxf(mx1, __shfl_xor_sync(0xffffffffu, mx1, 1));
        mx1 = fmaxf(mx1, __shfl_xor_sync(0xffffffffu, mx1, 2));
        float nm0 = fmaxf(m0, mx0), nm1 = fmaxf(m1, mx1);
        float e0 = __expf(m0 - nm0), e1 = __expf(m1 - nm1);
        float rs0 = 0.0f, rs1 = 0.0f;
#pragma unroll
        for (int nt = 0; nt < 8; nt++) {
            sv[nt][0] = __expf(sv[nt][0] - nm0); rs0 += sv[nt][0];
            sv[nt][1] = __expf(sv[nt][1] - nm0); rs0 += sv[nt][1];
            sv[nt][2] = __expf(sv[nt][2] - nm1); rs1 += sv[nt][2];
            sv[nt][3] = __expf(sv[nt][3] - nm1); rs1 += sv[nt][3];
        }
        rs0 += __shfl_xor_sync(0xffffffffu, rs0, 1);
        rs0 += __shfl_xor_sync(0xffffffffu, rs0, 2);
        rs1 += __shfl_xor_sync(0xffffffffu, rs1, 1);
        rs1 += __shfl_xor_sync(0xffffffffu, rs1, 2);
        l0v = l0v * e0 + rs0;
        l1v = l1v * e1 + rs1;
        m0 = nm0; m1 = nm1;
#pragma unroll
        for (int nt = 0; nt < 8; nt++) {
            o[nt][0] *= e0; o[nt][1] *= e0;
            o[nt][2] *= e1; o[nt][3] *= e1;
        }

        // ---- O += P @ V (P fragments straight from S accumulators) ----
        const uint32_t vbase_h = sb + AKV0 + (uint32_t)s * AKV_STAGE + 18432;
        const uint32_t vbase_l = vbase_h + 9216;
#pragma unroll
        for (int ks = 0; ks < 4; ks++) {
            uint32_t ph[4], pl[4];
            {
                __nv_bfloat16 ha, la, hb, lb;
                splitf(sv[2*ks][0], ha, la); splitf(sv[2*ks][1], hb, lb);
                ph[0] = packbf(ha, hb); pl[0] = packbf(la, lb);
                splitf(sv[2*ks][2], ha, la); splitf(sv[2*ks][3], hb, lb);
                ph[1] = packbf(ha, hb); pl[1] = packbf(la, lb);
                splitf(sv[2*ks+1][0], ha, la); splitf(sv[2*ks+1][1], hb, lb);
                ph[2] = packbf(ha, hb); pl[2] = packbf(la, lb);
                splitf(sv[2*ks+1][2], ha, la); splitf(sv[2*ks+1][3], hb, lb);
                ph[3] = packbf(ha, hb); pl[3] = packbf(la, lb);
            }
            const uint32_t vrow = (uint32_t)(16 * ks + vrow_off);
#pragma unroll
            for (int p2 = 0; p2 < 4; p2++) {
                uint32_t off = vrow * 144 + (uint32_t)p2 * 32 + vcolb;
                uint32_t h0, h1, h2, h3, q0, q1, q2, q3;
                ldmx4t(h0, h1, h2, h3, vbase_h + off);
                ldmx4t(q0, q1, q2, q3, vbase_l + off);
                uint32_t bbh0[2] = { h0, h1 }, bbh1[2] = { h2, h3 };
                uint32_t bbl0[2] = { q0, q1 }, bbl1[2] = { q2, q3 };
                // distance-2 chains
                mma_bf16(o[2*p2],     ph, bbh0);
                mma_bf16(o[2*p2+1],   ph, bbh1);
                mma_bf16(o[2*p2],     pl, bbh0);
                mma_bf16(o[2*p2+1],   pl, bbh1);
                mma_bf16(o[2*p2],     ph, bbl0);
                mma_bf16(o[2*p2+1],   ph, bbl1);
            }
        }
    }
#undef LOAD_KV

    // ---- epilogue: normalize, split, store bf16 hi/lo ----
    const float inv0 = 1.0f / l0v, inv1 = 1.0f / l1v;
    __nv_bfloat16* Oh = g_ah + hoff;
    __nv_bfloat16* Ol = g_al + hoff;
#pragma unroll
    for (int nt = 0; nt < 8; nt++) {
        int cg = nt * 8 + 2 * tg;
        __nv_bfloat16 ha, la, hb, lb;
        splitf(o[nt][0] * inv0, ha, la);
        splitf(o[nt][1] * inv0, hb, lb);
        *(uint32_t*)&Oh[(size_t)grow0 * 1024 + cg] = packbf(ha, hb);
        *(uint32_t*)&Ol[(size_t)grow0 * 1024 + cg] = packbf(la, lb);
        splitf(o[nt][2] * inv1, ha, la);
        splitf(o[nt][3] * inv1, hb, lb);
        *(uint32_t*)&Oh[(size_t)grow1 * 1024 + cg] = packbf(ha, hb);
        *(uint32_t*)&Ol[(size_t)grow1 * 1024 + cg] = packbf(la, lb);
    }
}

// ---------------------------------------------------------------------------
extern "C" void kernel_launch(void* const* d_in, const int* in_sizes, int n_in,
                              void* d_out, int out_size)
{
    (void)in_sizes; (void)n_in; (void)out_size;
    const float* x  = (const float*)d_in[0];
    const float* wq = (const float*)d_in[1];
    const float* wk = (const float*)d_in[2];
    const float* wv = (const float*)d_in[3];
    const float* wo = (const float*)d_in[4];
    float* out = (float*)d_out;

    cudaFuncSetAttribute(proj_kernel,
                         cudaFuncAttributeMaxDynamicSharedMemorySize, GEMM_SMEM);
    cudaFuncSetAttribute(oproj_kernel,
                         cudaFuncAttributeMaxDynamicSharedMemorySize, GEMM_SMEM);
    cudaFuncSetAttribute(attn_kernel,
                         cudaFuncAttributeMaxDynamicSharedMemorySize, ATTN_SMEM);

    split_kernel<<<8192, 256>>>(x, wq, wk, wv, wo);
    proj_kernel<<<dim3(8, 32, 3), 256, GEMM_SMEM>>>();
    attn_kernel<<<dim3(16, 32), 256, ATTN_SMEM>>>();
    oproj_kernel<<<dim3(8, 32), 256, GEMM_SMEM>>>(out);
}

// round 9
// speedup vs baseline: 1.2950x; 1.2297x over previous
#include <cuda_runtime.h>
#include <cuda_fp16.h>
#include <cstdint>
#include <math.h>

#define DMODEL 1024
#define NHEADS 16
#define DK     64
#define SEQ    2048
#define BATCH  2
#define MTOT   (BATCH*SEQ)   // 4096

// ---------------------------------------------------------------------------
// Global fp16 scratch (hi/lo split pairs; weights: hi only)
// ---------------------------------------------------------------------------
__device__ __half g_xh[MTOT*DMODEL], g_xl[MTOT*DMODEL];
__device__ __half g_wh[4*DMODEL*DMODEL];
__device__ __half g_qh[MTOT*DMODEL], g_ql[MTOT*DMODEL];
__device__ __half g_kh[MTOT*DMODEL], g_kl[MTOT*DMODEL];
__device__ __half g_vh[MTOT*DMODEL], g_vl[MTOT*DMODEL];
__device__ __half g_ah[MTOT*DMODEL], g_al[MTOT*DMODEL];

// ---------------------------------------------------------------------------
// Helpers
// ---------------------------------------------------------------------------
static __device__ __forceinline__ uint32_t s2u(const void* p) {
    uint32_t a;
    asm("{ .reg .u64 t; cvta.to.shared.u64 t, %1; cvt.u32.u64 %0, t; }"
        : "=r"(a) : "l"(p));
    return a;
}

#define CPA(dst, src) \
    asm volatile("cp.async.cg.shared.global [%0], [%1], 16;" \
                 :: "r"(dst), "l"(__cvta_generic_to_global(src)) : "memory")
#define CPC() asm volatile("cp.async.commit_group;" ::: "memory")
#define CPW(n) asm volatile("cp.async.wait_group %0;" :: "n"(n) : "memory")

static __device__ __forceinline__ void mma_f16(float* c, const uint32_t* a,
                                               const uint32_t* b) {
    asm volatile(
        "mma.sync.aligned.m16n8k16.row.col.f32.f16.f16.f32 "
        "{%0,%1,%2,%3}, {%4,%5,%6,%7}, {%8,%9}, {%0,%1,%2,%3};"
        : "+f"(c[0]), "+f"(c[1]), "+f"(c[2]), "+f"(c[3])
        : "r"(a[0]), "r"(a[1]), "r"(a[2]), "r"(a[3]), "r"(b[0]), "r"(b[1]));
}

static __device__ __forceinline__ void ldmx4t(uint32_t& r0, uint32_t& r1,
                                              uint32_t& r2, uint32_t& r3,
                                              uint32_t a) {
    asm volatile(
        "ldmatrix.sync.aligned.m8n8.x4.trans.shared.b16 {%0,%1,%2,%3}, [%4];"
        : "=r"(r0), "=r"(r1), "=r"(r2), "=r"(r3) : "r"(a));
}

static __device__ __forceinline__ void splitf(float v, __half& h, __half& l) {
    h = __float2half_rn(v);
    l = __float2half_rn(v - __half2float(h));
}

static __device__ __forceinline__ uint32_t packh(__half lo, __half hi) {
    __half2 t;
    t.x = lo; t.y = hi;
    return *(uint32_t*)&t;
}

// ---------------------------------------------------------------------------
// Split kernel: fp32 -> fp16. x: hi+lo; weights: hi only. 8192 blocks.
// ---------------------------------------------------------------------------
__global__ void __launch_bounds__(256)
split_kernel(const float* __restrict__ x,  const float* __restrict__ wq,
             const float* __restrict__ wk, const float* __restrict__ wv,
             const float* __restrict__ wo)
{
    int bid = blockIdx.x;
    if (bid < 4096) {
        int i = bid * 256 + threadIdx.x;
        float4 v = ((const float4*)x)[i];
        __half h0, l0, h1, l1, h2, l2, h3, l3;
        splitf(v.x, h0, l0); splitf(v.y, h1, l1);
        splitf(v.z, h2, l2); splitf(v.w, h3, l3);
        ((uint2*)g_xh)[i] = make_uint2(packh(h0, h1), packh(h2, h3));
        ((uint2*)g_xl)[i] = make_uint2(packh(l0, l1), packh(l2, l3));
    } else {
        int t = bid - 4096;
        int w = t >> 10;
        const float* ws = (w == 0) ? wq : (w == 1) ? wk : (w == 2) ? wv : wo;
        int i = (t & 1023) * 256 + threadIdx.x;
        float4 v = ((const float4*)ws)[i];
        uint2* dh = (uint2*)(g_wh + ((size_t)w << 20));
        dh[i] = make_uint2(packh(__float2half_rn(v.x), __float2half_rn(v.y)),
                           packh(__float2half_rn(v.z), __float2half_rn(v.w)));
    }
}

// ---------------------------------------------------------------------------
// fp16 2-pass GEMM: C = (Ah+Al) * Bh^T. CTA 128x128, BK=32, cp.async dbuf.
// ---------------------------------------------------------------------------
#define RS 40
#define GA_STAGE 10240                   // bytes per array per stage
#define G_STAGE  30720                   // Ah | Al | Bh
#define GEMM_SMEM (2*G_STAGE)            // 61440

template<bool SPLIT_OUT>
static __device__ void gemm_core(const __half* __restrict__ Ah,
                                 const __half* __restrict__ Al,
                                 const __half* __restrict__ Bh,
                                 __half* __restrict__ Ch,
                                 __half* __restrict__ Cl,
                                 float* __restrict__ Cf)
{
    extern __shared__ char smem[];
    const uint32_t sb = s2u(smem);
    const int tid  = threadIdx.x;
    const int lane = tid & 31;
    const int warp = tid >> 5;
    const int wy = warp >> 1, wx = warp & 1;
    const int gi = lane >> 2, tg = lane & 3;
    const int row0 = blockIdx.y * 128;
    const int col0 = blockIdx.x * 128;

    float acc[2][8][4];
#pragma unroll
    for (int mt = 0; mt < 2; mt++)
#pragma unroll
        for (int nt = 0; nt < 8; nt++)
#pragma unroll
            for (int r = 0; r < 4; r++) acc[mt][nt][r] = 0.0f;

#define GEMM_LOAD(kc, s)                                                     \
    {                                                                        \
        uint32_t d0 = sb + (uint32_t)(s) * G_STAGE;                          \
        _Pragma("unroll")                                                    \
        for (int c = 0; c < 2; c++) {                                        \
            int f = tid + c * 256;                                           \
            int row = f >> 2, seg = f & 3;                                   \
            size_t goA = (size_t)(row0 + row) * 1024 + (kc) * 32 + seg * 8;  \
            size_t goB = (size_t)(col0 + row) * 1024 + (kc) * 32 + seg * 8;  \
            uint32_t so = (uint32_t)(row * 80 + seg * 16);                   \
            CPA(d0 + so,                Ah + goA);                           \
            CPA(d0 + GA_STAGE + so,     Al + goA);                           \
            CPA(d0 + 2 * GA_STAGE + so, Bh + goB);                           \
        }                                                                    \
    }

    GEMM_LOAD(0, 0);
    CPC();

#pragma unroll 1
    for (int kc = 0; kc < 32; kc++) {
        const int s = kc & 1;
        CPW(0);
        __syncthreads();
        if (kc + 1 < 32) { GEMM_LOAD(kc + 1, s ^ 1); CPC(); }

        const uint16_t* sAh = (const uint16_t*)(smem + s * G_STAGE);
        const uint16_t* sAl = sAh + 5120;
        const uint16_t* sBh = sAh + 10240;

#pragma unroll
        for (int ks = 0; ks < 2; ks++) {
            const int cb = ks * 16 + 2 * tg;
            uint32_t afh[2][4], afl[2][4];
#pragma unroll
            for (int mt = 0; mt < 2; mt++) {
                int r = wy * 32 + mt * 16 + gi;
                afh[mt][0] = *(const uint32_t*)&sAh[r * RS + cb];
                afh[mt][1] = *(const uint32_t*)&sAh[(r + 8) * RS + cb];
                afh[mt][2] = *(const uint32_t*)&sAh[r * RS + cb + 8];
                afh[mt][3] = *(const uint32_t*)&sAh[(r + 8) * RS + cb + 8];
                afl[mt][0] = *(const uint32_t*)&sAl[r * RS + cb];
                afl[mt][1] = *(const uint32_t*)&sAl[(r + 8) * RS + cb];
                afl[mt][2] = *(const uint32_t*)&sAl[r * RS + cb + 8];
                afl[mt][3] = *(const uint32_t*)&sAl[(r + 8) * RS + cb + 8];
            }
            uint32_t bfh[8][2];
#pragma unroll
            for (int nt = 0; nt < 8; nt++) {
                int c = wx * 64 + nt * 8 + gi;
                bfh[nt][0] = *(const uint32_t*)&sBh[c * RS + cb];
                bfh[nt][1] = *(const uint32_t*)&sBh[c * RS + cb + 8];
            }
#pragma unroll
            for (int nt = 0; nt < 8; nt++)
#pragma unroll
                for (int mt = 0; mt < 2; mt++)
                    mma_f16(acc[mt][nt], afh[mt], bfh[nt]);
#pragma unroll
            for (int nt = 0; nt < 8; nt++)
#pragma unroll
                for (int mt = 0; mt < 2; mt++)
                    mma_f16(acc[mt][nt], afl[mt], bfh[nt]);
        }
    }

    // epilogue
#pragma unroll
    for (int mt = 0; mt < 2; mt++) {
        int r0g = row0 + wy * 32 + mt * 16 + gi;
#pragma unroll
        for (int nt = 0; nt < 8; nt++) {
            int cg = col0 + wx * 64 + nt * 8 + 2 * tg;
            if (SPLIT_OUT) {
                __half h0, l0, h1, l1;
                splitf(acc[mt][nt][0], h0, l0);
                splitf(acc[mt][nt][1], h1, l1);
                *(uint32_t*)&Ch[(size_t)r0g * 1024 + cg] = packh(h0, h1);
                *(uint32_t*)&Cl[(size_t)r0g * 1024 + cg] = packh(l0, l1);
                splitf(acc[mt][nt][2], h0, l0);
                splitf(acc[mt][nt][3], h1, l1);
                *(uint32_t*)&Ch[(size_t)(r0g + 8) * 1024 + cg] = packh(h0, h1);
                *(uint32_t*)&Cl[(size_t)(r0g + 8) * 1024 + cg] = packh(l0, l1);
            } else {
                *(float2*)&Cf[(size_t)r0g * 1024 + cg] =
                    make_float2(acc[mt][nt][0], acc[mt][nt][1]);
                *(float2*)&Cf[(size_t)(r0g + 8) * 1024 + cg] =
                    make_float2(acc[mt][nt][2], acc[mt][nt][3]);
            }
        }
    }
#undef GEMM_LOAD
}

__global__ void __launch_bounds__(256, 2)
proj_kernel()
{
    int z = blockIdx.z;
    const __half* Bh = g_wh + ((size_t)z << 20);
    __half* Ch = (z == 0) ? g_qh : (z == 1) ? g_kh : g_vh;
    __half* Cl = (z == 0) ? g_ql : (z == 1) ? g_kl : g_vl;
    gemm_core<true>(g_xh, g_xl, Bh, Ch, Cl, nullptr);
}

__global__ void __launch_bounds__(256, 2)
oproj_kernel(float* __restrict__ out)
{
    gemm_core<false>(g_ah, g_al, g_wh + ((size_t)3 << 20), nullptr, nullptr, out);
}

// ---------------------------------------------------------------------------
// Tensor-core flash attention (causal), fp16 3-pass. CTA = 128 q rows,
// 8 warps x 16 rows, key tiles of 64, register-resident P fragments.
// ---------------------------------------------------------------------------
#define AQH 0
#define AQL 18432
#define AKV0 36864
#define AKV_STAGE 36864
#define ATTN_SMEM (AKV0 + 2*AKV_STAGE)    // 110592

__global__ void __launch_bounds__(256, 2)
attn_kernel()
{
    extern __shared__ char smem[];
    const uint32_t sb = s2u(smem);
    const int tid  = threadIdx.x;
    const int lane = tid & 31;
    const int warp = tid >> 5;
    const int gi = lane >> 2, tg = lane & 3;

    const int qt = (int)gridDim.x - 1 - (int)blockIdx.x;   // big tiles first
    const int bh = blockIdx.y;
    const int b  = bh >> 4;
    const int h  = bh & 15;
    const size_t hoff = (size_t)b * SEQ * DMODEL + h * DK;

    const __half* Qh = g_qh + hoff;
    const __half* Ql = g_ql + hoff;
    const __half* Kh = g_kh + hoff;
    const __half* Kl = g_kl + hoff;
    const __half* Vh = g_vh + hoff;
    const __half* Vl = g_vl + hoff;

    const int row_base = qt * 128;
    const int ntiles = 2 * qt + 2;

    // prologue: Q tile (128x64 hi+lo)
#pragma unroll
    for (int c = 0; c < 4; c++) {
        int f = tid + c * 256;
        int row = f >> 3, seg = f & 7;
        size_t go = (size_t)(row_base + row) * 1024 + seg * 8;
        uint32_t so = (uint32_t)(row * 144 + seg * 16);
        CPA(sb + AQH + so, Qh + go);
        CPA(sb + AQL + so, Ql + go);
    }

#define LOAD_KV(jt, s)                                                     \
    {                                                                      \
        uint32_t d0 = sb + AKV0 + (uint32_t)(s) * AKV_STAGE;               \
        _Pragma("unroll")                                                  \
        for (int c = 0; c < 2; c++) {                                      \
            int f = tid + c * 256;                                         \
            int row = f >> 3, seg = f & 7;                                 \
            size_t go = (size_t)((jt) * 64 + row) * 1024 + seg * 8;        \
            uint32_t so = (uint32_t)(row * 144 + seg * 16);                \
            CPA(d0 + so,         Kh + go);                                 \
            CPA(d0 + 9216 + so,  Kl + go);                                 \
            CPA(d0 + 18432 + so, Vh + go);                                 \
            CPA(d0 + 27648 + so, Vl + go);                                 \
        }                                                                  \
    }

    LOAD_KV(0, 0);
    CPC();

    float o[8][4];
#pragma unroll
    for (int nt = 0; nt < 8; nt++)
#pragma unroll
        for (int r = 0; r < 4; r++) o[nt][r] = 0.0f;
    float m0 = -1e30f, m1 = -1e30f, l0v = 0.0f, l1v = 0.0f;

    const int r0 = warp * 16 + gi;
    const int r1 = r0 + 8;
    const int grow0 = row_base + r0;
    const int grow1 = row_base + r1;

    const int vrow_off = ((lane >> 3) & 1) * 8 + (lane & 7);
    const uint32_t vcolb = (uint32_t)((lane >> 4) * 16);

    const uint16_t* sQh = (const uint16_t*)(smem + AQH);
    const uint16_t* sQl = (const uint16_t*)(smem + AQL);

#pragma unroll 1
    for (int jt = 0; jt < ntiles; jt++) {
        const int s = jt & 1;
        CPW(0);
        __syncthreads();
        if (jt + 1 < ntiles) { LOAD_KV(jt + 1, s ^ 1); CPC(); }

        const uint16_t* sKh = (const uint16_t*)(smem + AKV0 + s * AKV_STAGE);
        const uint16_t* sKl = sKh + 4608;

        // ---- S = Q K^T ----
        float sv[8][4];
#pragma unroll
        for (int nt = 0; nt < 8; nt++)
#pragma unroll
            for (int r = 0; r < 4; r++) sv[nt][r] = 0.0f;

#pragma unroll
        for (int ks = 0; ks < 4; ks++) {
            const int cb = ks * 16 + 2 * tg;
            uint32_t ah_[4], al_[4];
            ah_[0] = *(const uint32_t*)&sQh[r0 * 72 + cb];
            ah_[1] = *(const uint32_t*)&sQh[r1 * 72 + cb];
            ah_[2] = *(const uint32_t*)&sQh[r0 * 72 + cb + 8];
            ah_[3] = *(const uint32_t*)&sQh[r1 * 72 + cb + 8];
            al_[0] = *(const uint32_t*)&sQl[r0 * 72 + cb];
            al_[1] = *(const uint32_t*)&sQl[r1 * 72 + cb];
            al_[2] = *(const uint32_t*)&sQl[r0 * 72 + cb + 8];
            al_[3] = *(const uint32_t*)&sQl[r1 * 72 + cb + 8];
#pragma unroll
            for (int g = 0; g < 4; g++) {
                int kr0 = (2 * g) * 8 + gi;
                int kr1 = (2 * g + 1) * 8 + gi;
                uint32_t bh0[2], bh1[2], bl0[2], bl1[2];
                bh0[0] = *(const uint32_t*)&sKh[kr0 * 72 + cb];
                bh0[1] = *(const uint32_t*)&sKh[kr0 * 72 + cb + 8];
                bh1[0] = *(const uint32_t*)&sKh[kr1 * 72 + cb];
                bh1[1] = *(const uint32_t*)&sKh[kr1 * 72 + cb + 8];
                bl0[0] = *(const uint32_t*)&sKl[kr0 * 72 + cb];
                bl0[1] = *(const uint32_t*)&sKl[kr0 * 72 + cb + 8];
                bl1[0] = *(const uint32_t*)&sKl[kr1 * 72 + cb];
                bl1[1] = *(const uint32_t*)&sKl[kr1 * 72 + cb + 8];
                mma_f16(sv[2 * g],     ah_, bh0);
                mma_f16(sv[2 * g + 1], ah_, bh1);
                mma_f16(sv[2 * g],     al_, bh0);
                mma_f16(sv[2 * g + 1], al_, bh1);
                mma_f16(sv[2 * g],     ah_, bl0);
                mma_f16(sv[2 * g + 1], ah_, bl1);
            }
        }

        // ---- scale + causal mask ----
        const bool maskt = (jt >= 2 * qt);
#pragma unroll
        for (int nt = 0; nt < 8; nt++) {
            sv[nt][0] *= 0.125f; sv[nt][1] *= 0.125f;
            sv[nt][2] *= 0.125f; sv[nt][3] *= 0.125f;
            if (maskt) {
                int c0 = jt * 64 + nt * 8 + 2 * tg;
                if (c0     > grow0) sv[nt][0] = -1e30f;
                if (c0 + 1 > grow0) sv[nt][1] = -1e30f;
                if (c0     > grow1) sv[nt][2] = -1e30f;
                if (c0 + 1 > grow1) sv[nt][3] = -1e30f;
            }
        }

        // ---- online softmax ----
        float mx0 = -1e30f, mx1 = -1e30f;
#pragma unroll
        for (int nt = 0; nt < 8; nt++) {
            mx0 = fmaxf(mx0, fmaxf(sv[nt][0], sv[nt][1]));
            mx1 = fmaxf(mx1, fmaxf(sv[nt][2], sv[nt][3]));
        }
        mx0 = fmaxf(mx0, __shfl_xor_sync(0xffffffffu, mx0, 1));
        mx0 = fmaxf(mx0, __shfl_xor_sync(0xffffffffu, mx0, 2));
        mx1 = fmaxf(mx1, __shfl_xor_sync(0xffffffffu, mx1, 1));
        mx1 = fmaxf(mx1, __shfl_xor_sync(0xffffffffu, mx1, 2));
        float nm0 = fmaxf(m0, mx0), nm1 = fmaxf(m1, mx1);
        float e0 = __expf(m0 - nm0), e1 = __expf(m1 - nm1);
        float rs0 = 0.0f, rs1 = 0.0f;
#pragma unroll
        for (int nt = 0; nt < 8; nt++) {
            sv[nt][0] = __expf(sv[nt][0] - nm0); rs0 += sv[nt][0];
            sv[nt][1] = __expf(sv[nt][1] - nm0); rs0 += sv[nt][1];
            sv[nt][2] = __expf(sv[nt][2] - nm1); rs1 += sv[nt][2];
            sv[nt][3] = __expf(sv[nt][3] - nm1); rs1 += sv[nt][3];
        }
        rs0 += __shfl_xor_sync(0xffffffffu, rs0, 1);
        rs0 += __shfl_xor_sync(0xffffffffu, rs0, 2);
        rs1 += __shfl_xor_sync(0xffffffffu, rs1, 1);
        rs1 += __shfl_xor_sync(0xffffffffu, rs1, 2);
        l0v = l0v * e0 + rs0;
        l1v = l1v * e1 + rs1;
        m0 = nm0; m1 = nm1;
#pragma unroll
        for (int nt = 0; nt < 8; nt++) {
            o[nt][0] *= e0; o[nt][1] *= e0;
            o[nt][2] *= e1; o[nt][3] *= e1;
        }

        // ---- O += P @ V ----
        const uint32_t vbase_h = sb + AKV0 + (uint32_t)s * AKV_STAGE + 18432;
        const uint32_t vbase_l = vbase_h + 9216;
#pragma unroll
        for (int ks = 0; ks < 4; ks++) {
            uint32_t ph[4], pl[4];
            {
                __half ha, la, hb, lb;
                splitf(sv[2*ks][0], ha, la); splitf(sv[2*ks][1], hb, lb);
                ph[0] = packh(ha, hb); pl[0] = packh(la, lb);
                splitf(sv[2*ks][2], ha, la); splitf(sv[2*ks][3], hb, lb);
                ph[1] = packh(ha, hb); pl[1] = packh(la, lb);
                splitf(sv[2*ks+1][0], ha, la); splitf(sv[2*ks+1][1], hb, lb);
                ph[2] = packh(ha, hb); pl[2] = packh(la, lb);
                splitf(sv[2*ks+1][2], ha, la); splitf(sv[2*ks+1][3], hb, lb);
                ph[3] = packh(ha, hb); pl[3] = packh(la, lb);
            }
            const uint32_t vrow = (uint32_t)(16 * ks + vrow_off);
#pragma unroll
            for (int p2 = 0; p2 < 4; p2++) {
                uint32_t off = vrow * 144 + (uint32_t)p2 * 32 + vcolb;
                uint32_t h0, h1, h2, h3, q0, q1, q2, q3;
                ldmx4t(h0, h1, h2, h3, vbase_h + off);
                ldmx4t(q0, q1, q2, q3, vbase_l + off);
                uint32_t bbh0[2] = { h0, h1 }, bbh1[2] = { h2, h3 };
                uint32_t bbl0[2] = { q0, q1 }, bbl1[2] = { q2, q3 };
                mma_f16(o[2*p2],     ph, bbh0);
                mma_f16(o[2*p2+1],   ph, bbh1);
                mma_f16(o[2*p2],     pl, bbh0);
                mma_f16(o[2*p2+1],   pl, bbh1);
                mma_f16(o[2*p2],     ph, bbl0);
                mma_f16(o[2*p2+1],   ph, bbl1);
            }
        }
    }
#undef LOAD_KV

    // ---- epilogue: normalize, split, store fp16 hi/lo ----
    const float inv0 = 1.0f / l0v, inv1 = 1.0f / l1v;
    __half* Oh = g_ah + hoff;
    __half* Ol = g_al + hoff;
#pragma unroll
    for (int nt = 0; nt < 8; nt++) {
        int cg = nt * 8 + 2 * tg;
        __half ha, la, hb, lb;
        splitf(o[nt][0] * inv0, ha, la);
        splitf(o[nt][1] * inv0, hb, lb);
        *(uint32_t*)&Oh[(size_t)grow0 * 1024 + cg] = packh(ha, hb);
        *(uint32_t*)&Ol[(size_t)grow0 * 1024 + cg] = packh(la, lb);
        splitf(o[nt][2] * inv1, ha, la);
        splitf(o[nt][3] * inv1, hb, lb);
        *(uint32_t*)&Oh[(size_t)grow1 * 1024 + cg] = packh(ha, hb);
        *(uint32_t*)&Ol[(size_t)grow1 * 1024 + cg] = packh(la, lb);
    }
}

// ---------------------------------------------------------------------------
extern "C" void kernel_launch(void* const* d_in, const int* in_sizes, int n_in,
                              void* d_out, int out_size)
{
    (void)in_sizes; (void)n_in; (void)out_size;
    const float* x  = (const float*)d_in[0];
    const float* wq = (const float*)d_in[1];
    const float* wk = (const float*)d_in[2];
    const float* wv = (const float*)d_in[3];
    const float* wo = (const float*)d_in[4];
    float* out = (float*)d_out;

    cudaFuncSetAttribute(proj_kernel,
                         cudaFuncAttributeMaxDynamicSharedMemorySize, GEMM_SMEM);
    cudaFuncSetAttribute(oproj_kernel,
                         cudaFuncAttributeMaxDynamicSharedMemorySize, GEMM_SMEM);
    cudaFuncSetAttribute(attn_kernel,
                         cudaFuncAttributeMaxDynamicSharedMemorySize, ATTN_SMEM);

    split_kernel<<<8192, 256>>>(x, wq, wk, wv, wo);
    proj_kernel<<<dim3(8, 32, 3), 256, GEMM_SMEM>>>();
    attn_kernel<<<dim3(16, 32), 256, ATTN_SMEM>>>();
    oproj_kernel<<<dim3(8, 32), 256, GEMM_SMEM>>>(out);
}

// round 10
// speedup vs baseline: 1.4698x; 1.1350x over previous
#include <cuda_runtime.h>
#include <cuda_fp16.h>
#include <cstdint>
#include <math.h>

#define DMODEL 1024
#define NHEADS 16
#define DK     64
#define SEQ    2048
#define BATCH  2
#define MTOT   (BATCH*SEQ)   // 4096

// ---------------------------------------------------------------------------
// Global fp16 scratch. x: hi/lo; weights: hi; q: hi/lo; k,v: hi; attn out: hi/lo
// ---------------------------------------------------------------------------
__device__ __half g_xh[MTOT*DMODEL], g_xl[MTOT*DMODEL];
__device__ __half g_wh[4*DMODEL*DMODEL];
__device__ __half g_qh[MTOT*DMODEL], g_ql[MTOT*DMODEL];
__device__ __half g_kh[MTOT*DMODEL];
__device__ __half g_vh[MTOT*DMODEL];
__device__ __half g_ah[MTOT*DMODEL], g_al[MTOT*DMODEL];

// ---------------------------------------------------------------------------
// Helpers
// ---------------------------------------------------------------------------
static __device__ __forceinline__ uint32_t s2u(const void* p) {
    uint32_t a;
    asm("{ .reg .u64 t; cvta.to.shared.u64 t, %1; cvt.u32.u64 %0, t; }"
        : "=r"(a) : "l"(p));
    return a;
}

#define CPA(dst, src) \
    asm volatile("cp.async.cg.shared.global [%0], [%1], 16;" \
                 :: "r"(dst), "l"(__cvta_generic_to_global(src)) : "memory")
#define CPC() asm volatile("cp.async.commit_group;" ::: "memory")
#define CPW(n) asm volatile("cp.async.wait_group %0;" :: "n"(n) : "memory")

static __device__ __forceinline__ void mma_f16(float* c, const uint32_t* a,
                                               const uint32_t* b) {
    asm volatile(
        "mma.sync.aligned.m16n8k16.row.col.f32.f16.f16.f32 "
        "{%0,%1,%2,%3}, {%4,%5,%6,%7}, {%8,%9}, {%0,%1,%2,%3};"
        : "+f"(c[0]), "+f"(c[1]), "+f"(c[2]), "+f"(c[3])
        : "r"(a[0]), "r"(a[1]), "r"(a[2]), "r"(a[3]), "r"(b[0]), "r"(b[1]));
}

static __device__ __forceinline__ void ldmx4t(uint32_t& r0, uint32_t& r1,
                                              uint32_t& r2, uint32_t& r3,
                                              uint32_t a) {
    asm volatile(
        "ldmatrix.sync.aligned.m8n8.x4.trans.shared.b16 {%0,%1,%2,%3}, [%4];"
        : "=r"(r0), "=r"(r1), "=r"(r2), "=r"(r3) : "r"(a));
}

static __device__ __forceinline__ void splitf(float v, __half& h, __half& l) {
    h = __float2half_rn(v);
    l = __float2half_rn(v - __half2float(h));
}

static __device__ __forceinline__ uint32_t packh(__half lo, __half hi) {
    __half2 t;
    t.x = lo; t.y = hi;
    return *(uint32_t*)&t;
}

// ---------------------------------------------------------------------------
// Split kernel: fp32 -> fp16. x: hi+lo; weights: hi only. 8192 blocks.
// ---------------------------------------------------------------------------
__global__ void __launch_bounds__(256)
split_kernel(const float* __restrict__ x,  const float* __restrict__ wq,
             const float* __restrict__ wk, const float* __restrict__ wv,
             const float* __restrict__ wo)
{
    int bid = blockIdx.x;
    if (bid < 4096) {
        int i = bid * 256 + threadIdx.x;
        float4 v = ((const float4*)x)[i];
        __half h0, l0, h1, l1, h2, l2, h3, l3;
        splitf(v.x, h0, l0); splitf(v.y, h1, l1);
        splitf(v.z, h2, l2); splitf(v.w, h3, l3);
        ((uint2*)g_xh)[i] = make_uint2(packh(h0, h1), packh(h2, h3));
        ((uint2*)g_xl)[i] = make_uint2(packh(l0, l1), packh(l2, l3));
    } else {
        int t = bid - 4096;
        int w = t >> 10;
        const float* ws = (w == 0) ? wq : (w == 1) ? wk : (w == 2) ? wv : wo;
        int i = (t & 1023) * 256 + threadIdx.x;
        float4 v = ((const float4*)ws)[i];
        uint2* dh = (uint2*)(g_wh + ((size_t)w << 20));
        dh[i] = make_uint2(packh(__float2half_rn(v.x), __float2half_rn(v.y)),
                           packh(__float2half_rn(v.z), __float2half_rn(v.w)));
    }
}

// ---------------------------------------------------------------------------
// fp16 2-pass GEMM: C = (Ah+Al) * Bh^T. CTA 128x128, BK=32, cp.async dbuf.
// ---------------------------------------------------------------------------
#define RS 40
#define GA_STAGE 10240                   // bytes per array per stage
#define G_STAGE  30720                   // Ah | Al | Bh
#define GEMM_SMEM (2*G_STAGE)            // 61440

template<bool SPLIT_OUT>
static __device__ void gemm_core(const __half* __restrict__ Ah,
                                 const __half* __restrict__ Al,
                                 const __half* __restrict__ Bh,
                                 __half* __restrict__ Ch,
                                 __half* __restrict__ Cl,
                                 float* __restrict__ Cf)
{
    extern __shared__ char smem[];
    const uint32_t sb = s2u(smem);
    const int tid  = threadIdx.x;
    const int lane = tid & 31;
    const int warp = tid >> 5;
    const int wy = warp >> 1, wx = warp & 1;
    const int gi = lane >> 2, tg = lane & 3;
    const int row0 = blockIdx.y * 128;
    const int col0 = blockIdx.x * 128;

    float acc[2][8][4];
#pragma unroll
    for (int mt = 0; mt < 2; mt++)
#pragma unroll
        for (int nt = 0; nt < 8; nt++)
#pragma unroll
            for (int r = 0; r < 4; r++) acc[mt][nt][r] = 0.0f;

#define GEMM_LOAD(kc, s)                                                     \
    {                                                                        \
        uint32_t d0 = sb + (uint32_t)(s) * G_STAGE;                          \
        _Pragma("unroll")                                                    \
        for (int c = 0; c < 2; c++) {                                        \
            int f = tid + c * 256;                                           \
            int row = f >> 2, seg = f & 3;                                   \
            size_t goA = (size_t)(row0 + row) * 1024 + (kc) * 32 + seg * 8;  \
            size_t goB = (size_t)(col0 + row) * 1024 + (kc) * 32 + seg * 8;  \
            uint32_t so = (uint32_t)(row * 80 + seg * 16);                   \
            CPA(d0 + so,                Ah + goA);                           \
            CPA(d0 + GA_STAGE + so,     Al + goA);                           \
            CPA(d0 + 2 * GA_STAGE + so, Bh + goB);                           \
        }                                                                    \
    }

    GEMM_LOAD(0, 0);
    CPC();

#pragma unroll 1
    for (int kc = 0; kc < 32; kc++) {
        const int s = kc & 1;
        CPW(0);
        __syncthreads();
        if (kc + 1 < 32) { GEMM_LOAD(kc + 1, s ^ 1); CPC(); }

        const uint16_t* sAh = (const uint16_t*)(smem + s * G_STAGE);
        const uint16_t* sAl = sAh + 5120;
        const uint16_t* sBh = sAh + 10240;

#pragma unroll
        for (int ks = 0; ks < 2; ks++) {
            const int cb = ks * 16 + 2 * tg;
            uint32_t afh[2][4], afl[2][4];
#pragma unroll
            for (int mt = 0; mt < 2; mt++) {
                int r = wy * 32 + mt * 16 + gi;
                afh[mt][0] = *(const uint32_t*)&sAh[r * RS + cb];
                afh[mt][1] = *(const uint32_t*)&sAh[(r + 8) * RS + cb];
                afh[mt][2] = *(const uint32_t*)&sAh[r * RS + cb + 8];
                afh[mt][3] = *(const uint32_t*)&sAh[(r + 8) * RS + cb + 8];
                afl[mt][0] = *(const uint32_t*)&sAl[r * RS + cb];
                afl[mt][1] = *(const uint32_t*)&sAl[(r + 8) * RS + cb];
                afl[mt][2] = *(const uint32_t*)&sAl[r * RS + cb + 8];
                afl[mt][3] = *(const uint32_t*)&sAl[(r + 8) * RS + cb + 8];
            }
            uint32_t bfh[8][2];
#pragma unroll
            for (int nt = 0; nt < 8; nt++) {
                int c = wx * 64 + nt * 8 + gi;
                bfh[nt][0] = *(const uint32_t*)&sBh[c * RS + cb];
                bfh[nt][1] = *(const uint32_t*)&sBh[c * RS + cb + 8];
            }
#pragma unroll
            for (int nt = 0; nt < 8; nt++)
#pragma unroll
                for (int mt = 0; mt < 2; mt++)
                    mma_f16(acc[mt][nt], afh[mt], bfh[nt]);
#pragma unroll
            for (int nt = 0; nt < 8; nt++)
#pragma unroll
                for (int mt = 0; mt < 2; mt++)
                    mma_f16(acc[mt][nt], afl[mt], bfh[nt]);
        }
    }

    // epilogue
#pragma unroll
    for (int mt = 0; mt < 2; mt++) {
        int r0g = row0 + wy * 32 + mt * 16 + gi;
#pragma unroll
        for (int nt = 0; nt < 8; nt++) {
            int cg = col0 + wx * 64 + nt * 8 + 2 * tg;
            if (SPLIT_OUT) {
                __half h0, l0, h1, l1;
                splitf(acc[mt][nt][0], h0, l0);
                splitf(acc[mt][nt][1], h1, l1);
                *(uint32_t*)&Ch[(size_t)r0g * 1024 + cg] = packh(h0, h1);
                if (Cl) *(uint32_t*)&Cl[(size_t)r0g * 1024 + cg] = packh(l0, l1);
                splitf(acc[mt][nt][2], h0, l0);
                splitf(acc[mt][nt][3], h1, l1);
                *(uint32_t*)&Ch[(size_t)(r0g + 8) * 1024 + cg] = packh(h0, h1);
                if (Cl) *(uint32_t*)&Cl[(size_t)(r0g + 8) * 1024 + cg] = packh(l0, l1);
            } else {
                *(float2*)&Cf[(size_t)r0g * 1024 + cg] =
                    make_float2(acc[mt][nt][0], acc[mt][nt][1]);
                *(float2*)&Cf[(size_t)(r0g + 8) * 1024 + cg] =
                    make_float2(acc[mt][nt][2], acc[mt][nt][3]);
            }
        }
    }
#undef GEMM_LOAD
}

__global__ void __launch_bounds__(256, 2)
proj_kernel()
{
    int z = blockIdx.z;
    const __half* Bh = g_wh + ((size_t)z << 20);
    __half* Ch = (z == 0) ? g_qh : (z == 1) ? g_kh : g_vh;
    __half* Cl = (z == 0) ? g_ql : nullptr;     // lo only needed for Q
    gemm_core<true>(g_xh, g_xl, Bh, Ch, Cl, nullptr);
}

__global__ void __launch_bounds__(256, 2)
oproj_kernel(float* __restrict__ out)
{
    gemm_core<false>(g_ah, g_al, g_wh + ((size_t)3 << 20), nullptr, nullptr, out);
}

// ---------------------------------------------------------------------------
// Tensor-core flash attention (causal), 2-pass fp16:
//   S = (Qh+Ql)·Kh,  O += (Ph+Pl)·Vh.
// CTA = 128 q rows, 8 warps x 16 rows, key tiles of 64.
// ---------------------------------------------------------------------------
#define AQH 0
#define AQL 18432
#define AKV0 36864
#define AKV_STAGE 18432                   // Kh | Vh (9216 each)
#define ATTN_SMEM (AKV0 + 2*AKV_STAGE)    // 73728

__global__ void __launch_bounds__(256, 2)
attn_kernel()
{
    extern __shared__ char smem[];
    const uint32_t sb = s2u(smem);
    const int tid  = threadIdx.x;
    const int lane = tid & 31;
    const int warp = tid >> 5;
    const int gi = lane >> 2, tg = lane & 3;

    const int qt = (int)gridDim.x - 1 - (int)blockIdx.x;   // big tiles first
    const int bh = blockIdx.y;
    const int b  = bh >> 4;
    const int h  = bh & 15;
    const size_t hoff = (size_t)b * SEQ * DMODEL + h * DK;

    const __half* Qh = g_qh + hoff;
    const __half* Ql = g_ql + hoff;
    const __half* Kh = g_kh + hoff;
    const __half* Vh = g_vh + hoff;

    const int row_base = qt * 128;
    const int ntiles = 2 * qt + 2;

    // prologue: Q tile (128x64 hi+lo)
#pragma unroll
    for (int c = 0; c < 4; c++) {
        int f = tid + c * 256;
        int row = f >> 3, seg = f & 7;
        size_t go = (size_t)(row_base + row) * 1024 + seg * 8;
        uint32_t so = (uint32_t)(row * 144 + seg * 16);
        CPA(sb + AQH + so, Qh + go);
        CPA(sb + AQL + so, Ql + go);
    }

#define LOAD_KV(jt, s)                                                     \
    {                                                                      \
        uint32_t d0 = sb + AKV0 + (uint32_t)(s) * AKV_STAGE;               \
        _Pragma("unroll")                                                  \
        for (int c = 0; c < 2; c++) {                                      \
            int f = tid + c * 256;                                         \
            int row = f >> 3, seg = f & 7;                                 \
            size_t go = (size_t)((jt) * 64 + row) * 1024 + seg * 8;        \
            uint32_t so = (uint32_t)(row * 144 + seg * 16);                \
            CPA(d0 + so,        Kh + go);                                  \
            CPA(d0 + 9216 + so, Vh + go);                                  \
        }                                                                  \
    }

    LOAD_KV(0, 0);
    CPC();

    float o[8][4];
#pragma unroll
    for (int nt = 0; nt < 8; nt++)
#pragma unroll
        for (int r = 0; r < 4; r++) o[nt][r] = 0.0f;
    float m0 = -1e30f, m1 = -1e30f, l0v = 0.0f, l1v = 0.0f;

    const int r0 = warp * 16 + gi;
    const int r1 = r0 + 8;
    const int grow0 = row_base + r0;
    const int grow1 = row_base + r1;

    const int vrow_off = ((lane >> 3) & 1) * 8 + (lane & 7);
    const uint32_t vcolb = (uint32_t)((lane >> 4) * 16);

    const uint16_t* sQh = (const uint16_t*)(smem + AQH);
    const uint16_t* sQl = (const uint16_t*)(smem + AQL);

#pragma unroll 1
    for (int jt = 0; jt < ntiles; jt++) {
        const int s = jt & 1;
        CPW(0);
        __syncthreads();
        if (jt + 1 < ntiles) { LOAD_KV(jt + 1, s ^ 1); CPC(); }

        const uint16_t* sKh = (const uint16_t*)(smem + AKV0 + s * AKV_STAGE);

        // ---- S = (Qh+Ql) Kh^T ----
        float sv[8][4];
#pragma unroll
        for (int nt = 0; nt < 8; nt++)
#pragma unroll
            for (int r = 0; r < 4; r++) sv[nt][r] = 0.0f;

#pragma unroll
        for (int ks = 0; ks < 4; ks++) {
            const int cb = ks * 16 + 2 * tg;
            uint32_t ah_[4], al_[4];
            ah_[0] = *(const uint32_t*)&sQh[r0 * 72 + cb];
            ah_[1] = *(const uint32_t*)&sQh[r1 * 72 + cb];
            ah_[2] = *(const uint32_t*)&sQh[r0 * 72 + cb + 8];
            ah_[3] = *(const uint32_t*)&sQh[r1 * 72 + cb + 8];
            al_[0] = *(const uint32_t*)&sQl[r0 * 72 + cb];
            al_[1] = *(const uint32_t*)&sQl[r1 * 72 + cb];
            al_[2] = *(const uint32_t*)&sQl[r0 * 72 + cb + 8];
            al_[3] = *(const uint32_t*)&sQl[r1 * 72 + cb + 8];
#pragma unroll
            for (int g = 0; g < 4; g++) {
                int kr0 = (2 * g) * 8 + gi;
                int kr1 = (2 * g + 1) * 8 + gi;
                uint32_t bh0[2], bh1[2];
                bh0[0] = *(const uint32_t*)&sKh[kr0 * 72 + cb];
                bh0[1] = *(const uint32_t*)&sKh[kr0 * 72 + cb + 8];
                bh1[0] = *(const uint32_t*)&sKh[kr1 * 72 + cb];
                bh1[1] = *(const uint32_t*)&sKh[kr1 * 72 + cb + 8];
                mma_f16(sv[2 * g],     ah_, bh0);
                mma_f16(sv[2 * g + 1], ah_, bh1);
                mma_f16(sv[2 * g],     al_, bh0);
                mma_f16(sv[2 * g + 1], al_, bh1);
            }
        }

        // ---- scale + causal mask ----
        const bool maskt = (jt >= 2 * qt);
#pragma unroll
        for (int nt = 0; nt < 8; nt++) {
            sv[nt][0] *= 0.125f; sv[nt][1] *= 0.125f;
            sv[nt][2] *= 0.125f; sv[nt][3] *= 0.125f;
            if (maskt) {
                int c0 = jt * 64 + nt * 8 + 2 * tg;
                if (c0     > grow0) sv[nt][0] = -1e30f;
                if (c0 + 1 > grow0) sv[nt][1] = -1e30f;
                if (c0     > grow1) sv[nt][2] = -1e30f;
                if (c0 + 1 > grow1) sv[nt][3] = -1e30f;
            }
        }

        // ---- online softmax ----
        float mx0 = -1e30f, mx1 = -1e30f;
#pragma unroll
        for (int nt = 0; nt < 8; nt++) {
            mx0 = fmaxf(mx0, fmaxf(sv[nt][0], sv[nt][1]));
            mx1 = fmaxf(mx1, fmaxf(sv[nt][2], sv[nt][3]));
        }
        mx0 = fmaxf(mx0, __shfl_xor_sync(0xffffffffu, mx0, 1));
        mx0 = fmaxf(mx0, __shfl_xor_sync(0xffffffffu, mx0, 2));
        mx1 = fmaxf(mx1, __shfl_xor_sync(0xffffffffu, mx1, 1));
        mx1 = fmaxf(mx1, __shfl_xor_sync(0xffffffffu, mx1, 2));
        float nm0 = fmaxf(m0, mx0), nm1 = fmaxf(m1, mx1);
        float e0 = __expf(m0 - nm0), e1 = __expf(m1 - nm1);
        float rs0 = 0.0f, rs1 = 0.0f;
#pragma unroll
        for (int nt = 0; nt < 8; nt++) {
            sv[nt][0] = __expf(sv[nt][0] - nm0); rs0 += sv[nt][0];
            sv[nt][1] = __expf(sv[nt][1] - nm0); rs0 += sv[nt][1];
            sv[nt][2] = __expf(sv[nt][2] - nm1); rs1 += sv[nt][2];
            sv[nt][3] = __expf(sv[nt][3] - nm1); rs1 += sv[nt][3];
        }
        rs0 += __shfl_xor_sync(0xffffffffu, rs0, 1);
        rs0 += __shfl_xor_sync(0xffffffffu, rs0, 2);
        rs1 += __shfl_xor_sync(0xffffffffu, rs1, 1);
        rs1 += __shfl_xor_sync(0xffffffffu, rs1, 2);
        l0v = l0v * e0 + rs0;
        l1v = l1v * e1 + rs1;
        m0 = nm0; m1 = nm1;
#pragma unroll
        for (int nt = 0; nt < 8; nt++) {
            o[nt][0] *= e0; o[nt][1] *= e0;
            o[nt][2] *= e1; o[nt][3] *= e1;
        }

        // ---- O += (Ph+Pl) Vh ----
        const uint32_t vbase_h = sb + AKV0 + (uint32_t)s * AKV_STAGE + 9216;
#pragma unroll
        for (int ks = 0; ks < 4; ks++) {
            uint32_t ph[4], pl[4];
            {
                __half ha, la, hb, lb;
                splitf(sv[2*ks][0], ha, la); splitf(sv[2*ks][1], hb, lb);
                ph[0] = packh(ha, hb); pl[0] = packh(la, lb);
                splitf(sv[2*ks][2], ha, la); splitf(sv[2*ks][3], hb, lb);
                ph[1] = packh(ha, hb); pl[1] = packh(la, lb);
                splitf(sv[2*ks+1][0], ha, la); splitf(sv[2*ks+1][1], hb, lb);
                ph[2] = packh(ha, hb); pl[2] = packh(la, lb);
                splitf(sv[2*ks+1][2], ha, la); splitf(sv[2*ks+1][3], hb, lb);
                ph[3] = packh(ha, hb); pl[3] = packh(la, lb);
            }
            const uint32_t vrow = (uint32_t)(16 * ks + vrow_off);
#pragma unroll
            for (int p2 = 0; p2 < 4; p2++) {
                uint32_t off = vrow * 144 + (uint32_t)p2 * 32 + vcolb;
                uint32_t h0, h1, h2, h3;
                ldmx4t(h0, h1, h2, h3, vbase_h + off);
                uint32_t bbh0[2] = { h0, h1 }, bbh1[2] = { h2, h3 };
                mma_f16(o[2*p2],     ph, bbh0);
                mma_f16(o[2*p2+1],   ph, bbh1);
                mma_f16(o[2*p2],     pl, bbh0);
                mma_f16(o[2*p2+1],   pl, bbh1);
            }
        }
    }
#undef LOAD_KV

    // ---- epilogue: normalize, split, store fp16 hi/lo ----
    const float inv0 = 1.0f / l0v, inv1 = 1.0f / l1v;
    __half* Oh = g_ah + hoff;
    __half* Ol = g_al + hoff;
#pragma unroll
    for (int nt = 0; nt < 8; nt++) {
        int cg = nt * 8 + 2 * tg;
        __half ha, la, hb, lb;
        splitf(o[nt][0] * inv0, ha, la);
        splitf(o[nt][1] * inv0, hb, lb);
        *(uint32_t*)&Oh[(size_t)grow0 * 1024 + cg] = packh(ha, hb);
        *(uint32_t*)&Ol[(size_t)grow0 * 1024 + cg] = packh(la, lb);
        splitf(o[nt][2] * inv1, ha, la);
        splitf(o[nt][3] * inv1, hb, lb);
        *(uint32_t*)&Oh[(size_t)grow1 * 1024 + cg] = packh(ha, hb);
        *(uint32_t*)&Ol[(size_t)grow1 * 1024 + cg] = packh(la, lb);
    }
}

// ---------------------------------------------------------------------------
extern "C" void kernel_launch(void* const* d_in, const int* in_sizes, int n_in,
                              void* d_out, int out_size)
{
    (void)in_sizes; (void)n_in; (void)out_size;
    const float* x  = (const float*)d_in[0];
    const float* wq = (const float*)d_in[1];
    const float* wk = (const float*)d_in[2];
    const float* wv = (const float*)d_in[3];
    const float* wo = (const float*)d_in[4];
    float* out = (float*)d_out;

    cudaFuncSetAttribute(proj_kernel,
                         cudaFuncAttributeMaxDynamicSharedMemorySize, GEMM_SMEM);
    cudaFuncSetAttribute(oproj_kernel,
                         cudaFuncAttributeMaxDynamicSharedMemorySize, GEMM_SMEM);
    cudaFuncSetAttribute(attn_kernel,
                         cudaFuncAttributeMaxDynamicSharedMemorySize, ATTN_SMEM);

    split_kernel<<<8192, 256>>>(x, wq, wk, wv, wo);
    proj_kernel<<<dim3(8, 32, 3), 256, GEMM_SMEM>>>();
    attn_kernel<<<dim3(16, 32), 256, ATTN_SMEM>>>();
    oproj_kernel<<<dim3(8, 32), 256, GEMM_SMEM>>>(out);
}